// round 15
// baseline (speedup 1.0000x reference)
#include <cuda_runtime.h>
#include <cstdint>

#define N_NODES 100000
#define N_EDGES 20000
#define NNZ     1000000
#define D       64
#define ESTRIDE 112          // max incidences per edge bin (Poisson(50), ~9 sigma)
#define VSTRIDE 40           // max incidences per vertex bin (Poisson(10), ~9 sigma)

#define NPRE    65           // fat1: pre blocks
#define NFILL   1954         // fat1: fill blocks
#define NPRE2   17           // fat2b: pre2 blocks
#define NGE     1250         // fat2b: gather_e blocks
#define NEDGEG  625          // fat3: edge gemm blocks (20000/32)
#define NNODEG  1563         // fat3: node gemm blocks (ceil(100000/64))
#define SYNC_TARGET (NPRE2 + NGE)   // fat2b block count

// ---------------- scratch (device globals; allocation-free) ----------------
// g_cnt layout: [0:E) edge counts | [E:E+N) vertex counts | [E+N] sync flag
__device__ int   g_cnt[N_EDGES + N_NODES + 1];
__device__ int   g_adj_e[N_EDGES * ESTRIDE];
__device__ int   g_adj_v[N_NODES * VSTRIDE];
__device__ float g_Xsum[N_EDGES * D];       // per-edge sum of X rows
__device__ float g_Z   [N_EDGES * D];       // Xsum @ W1Bf + deg*bZ
__device__ float g_P1  [N_NODES * D];       // 0.5*(X@A) + 0.5*cvec
__device__ float g_P2  [N_NODES * D];       // 0.5*(X0@W^T) + Wb
__device__ float g_W1T [D * D];             // W1_w transposed [k][j]
__device__ float g_Bf  [D * D];             // W2b^T @ W^T
__device__ float g_W1Bf[D * D];             // W1T @ Bf
__device__ float g_bZ  [D];                 // b1 @ Bf
__device__ float g_WcatA[128 * D];          // [A | W^T] stacked, [k][j]
__device__ float g_cvec[D];                 // b2 @ W^T

#define GDC_LAUNCH_DEPENDENTS() \
    asm volatile("griddepcontrol.launch_dependents;")
#define GDC_WAIT() \
    asm volatile("griddepcontrol.wait;" ::: "memory")

// ---------------------------------------------------------------------------
// fat1: blocks [0, NPRE) = weight folding stage 1 (16KB smem); rest = fill.
// Signals dependent launch (fat2b) at end of each block's work.
// ---------------------------------------------------------------------------
__global__ __launch_bounds__(256) void k_fat1(const int* __restrict__ vertex,
                                              const int* __restrict__ edges,
                                              const float* __restrict__ W1_w,
                                              const float* __restrict__ W2_w,
                                              const float* __restrict__ W2_b,
                                              const float* __restrict__ W_w) {
    __shared__ float WT[64 * 64];   // WT[m][j] = W_w[j][m]
    int b = blockIdx.x;
    int tid = threadIdx.x;
    if (b < NPRE) {
        for (int i = tid; i < 4096; i += 256) {
            int j = i >> 6, m = i & 63;
            WT[m * 64 + j] = W_w[i];
        }
        __syncthreads();
        int idx = b * 256 + tid;
        if (idx < 4096) {                              // A = W2a^T @ W^T
            int k = idx >> 6, j = idx & 63;
            float acc = 0.f;
            #pragma unroll 8
            for (int m = 0; m < 64; m++) acc += W2_w[m * 128 + k] * WT[m * 64 + j];
            g_WcatA[idx] = acc;
        } else if (idx < 8192) {                       // W^T copy
            int t = idx - 4096;
            g_WcatA[4096 + t] = WT[t];
        } else if (idx < 12288) {                      // Bf = W2b^T @ W^T
            int t = idx - 8192;
            int k = t >> 6, j = t & 63;
            float acc = 0.f;
            #pragma unroll 8
            for (int m = 0; m < 64; m++) acc += W2_w[m * 128 + 64 + k] * WT[m * 64 + j];
            g_Bf[t] = acc;
        } else if (idx < 16384) {                      // W1T
            int t = idx - 12288;
            int k = t >> 6, j = t & 63;
            g_W1T[k * 64 + j] = W1_w[j * 64 + k];
        } else if (idx < 16448) {                      // cvec
            int j = idx - 16384;
            float acc = 0.f;
            for (int m = 0; m < 64; m++) acc += W2_b[m] * WT[m * 64 + j];
            g_cvec[j] = acc;
        }
        GDC_LAUNCH_DEPENDENTS();
    } else {
        int i = (b - NPRE) * 256 + tid;
        if (i < NNZ / 2) {
            int* cur_e = g_cnt;
            int* cur_v = g_cnt + N_EDGES;
            int2 v2 = __ldg((const int2*)vertex + i);
            int2 e2 = __ldg((const int2*)edges + i);
            int se0 = atomicAdd(&cur_e[e2.x], 1);
            if (se0 < ESTRIDE) g_adj_e[e2.x * ESTRIDE + se0] = v2.x;
            int sv0 = atomicAdd(&cur_v[v2.x], 1);
            if (sv0 < VSTRIDE) g_adj_v[v2.x * VSTRIDE + sv0] = e2.x;
            int se1 = atomicAdd(&cur_e[e2.y], 1);
            if (se1 < ESTRIDE) g_adj_e[e2.y * ESTRIDE + se1] = v2.y;
            int sv1 = atomicAdd(&cur_v[v2.y], 1);
            if (sv1 < VSTRIDE) g_adj_v[v2.y * VSTRIDE + sv1] = e2.y;
        }
        GDC_LAUNCH_DEPENDENTS();
    }
}

// float4 gather-accumulate, int4 index loads (segments are 16B-aligned:
// ESTRIDE=112 and VSTRIDE=40 are both multiples of 4).
__device__ __forceinline__ float4 gather_rows(const int* __restrict__ adj, int d,
                                              const float4* __restrict__ S4,
                                              int lane) {
    float4 acc = make_float4(0.f, 0.f, 0.f, 0.f);
    int j = 0;
    for (; j + 4 <= d; j += 4) {
        int4 a4 = *(const int4*)(adj + j);
        float4 x0 = S4[(size_t)a4.x * 16 + lane];
        float4 x1 = S4[(size_t)a4.y * 16 + lane];
        float4 x2 = S4[(size_t)a4.z * 16 + lane];
        float4 x3 = S4[(size_t)a4.w * 16 + lane];
        acc.x += (x0.x + x1.x) + (x2.x + x3.x);
        acc.y += (x0.y + x1.y) + (x2.y + x3.y);
        acc.z += (x0.z + x1.z) + (x2.z + x3.z);
        acc.w += (x0.w + x1.w) + (x2.w + x3.w);
    }
    for (; j < d; j++) {
        int a0 = __ldg(adj + j);
        float4 x0 = S4[(size_t)a0 * 16 + lane];
        acc.x += x0.x; acc.y += x0.y; acc.z += x0.z; acc.w += x0.w;
    }
    return acc;
}

// ---------------------------------------------------------------------------
// fat2b: waits on fat1 (PDL), then immediately signals fat3 (node blocks of
// fat3 depend only on fat1, which is complete once our wait releases).
// blocks [0,NPRE2) = pre2 (W1Bf, bZ); rest = gather_e. After its work, every
// block release-increments the sync flag consumed by fat3's edge blocks.
// ---------------------------------------------------------------------------
__global__ __launch_bounds__(256) void k_fat2b(const float* __restrict__ X,
                                               const float* __restrict__ W1_b) {
    __shared__ float Bfs[64 * 64];
    int b = blockIdx.x;
    int tid = threadIdx.x;
    GDC_WAIT();                 // fat1 fully complete (adjacency + weights)
    GDC_LAUNCH_DEPENDENTS();    // release fat3 (node blocks need only fat1)
    if (b < NPRE2) {
        for (int i = tid; i < 4096; i += 256) Bfs[i] = g_Bf[i];
        __syncthreads();
        int idx = b * 256 + tid;
        if (idx < 4096) {
            int k = idx >> 6, j = idx & 63;
            float acc = 0.f;
            #pragma unroll 8
            for (int m = 0; m < 64; m++) acc += __ldg(g_W1T + k * 64 + m) * Bfs[m * 64 + j];
            g_W1Bf[idx] = acc;
        } else if (idx < 4160) {
            int j = idx - 4096;
            float acc = 0.f;
            for (int m = 0; m < 64; m++) acc += __ldg(W1_b + m) * Bfs[m * 64 + j];
            g_bZ[j] = acc;
        }
    } else {
        // gather_e: one edge per half-warp
        int seg = (b - NPRE2) * 16 + (tid >> 4);
        int lane = tid & 15;
        int d = g_cnt[seg];
        if (d > ESTRIDE) d = ESTRIDE;
        float4 acc = gather_rows(g_adj_e + seg * ESTRIDE, d, (const float4*)X, lane);
        ((float4*)g_Xsum)[(size_t)seg * 16 + lane] = acc;
    }
    // release-signal: all this block's writes are visible before the increment
    __threadfence();
    __syncthreads();
    if (tid == 0) atomicAdd(&g_cnt[N_EDGES + N_NODES], 1);
}

#define FMA_X2(d, a, b) \
    asm("fma.rn.f32x2 %0, %1, %2, %0;" : "+l"(d) : "l"(a), "l"(b))

// fat3 union smem: edge 42112B, node 50688B
#define FAT3_SMEM 50688

// ---------------------------------------------------------------------------
// fat3 (PDL over fat2b): blocks [0, NNODEG) = node GEMM — depends only on
// fat1, overlaps fat2b's gather_e; blocks [NNODEG, +NEDGEG) = edge dual-GEMM
// — acquire-spin on fat2b's completion flag before reading its outputs.
// All blocks signal gatherv_out (PDL) after their stores.
// ---------------------------------------------------------------------------
__global__ __launch_bounds__(256) void k_fat3(const float* __restrict__ X,
                                              const float* __restrict__ X0,
                                              const float* __restrict__ W1_b,
                                              const float* __restrict__ Wb,
                                              float* __restrict__ XeOut) {
    extern __shared__ char sm_raw[];
    int b = blockIdx.x;
    int tid = threadIdx.x;

    if (b >= NNODEG) {
        // ------------------ edge dual GEMM (32-row tile) ------------------
        // acquire-spin: all SYNC_TARGET fat2b blocks have release-incremented
        if (tid == 0) {
            int v;
            do {
                asm volatile("ld.acquire.gpu.global.b32 %0, [%1];"
                             : "=r"(v) : "l"(&g_cnt[N_EDGES + N_NODES]));
                if (v < SYNC_TARGET) __nanosleep(64);
            } while (v < SYNC_TARGET);
        }
        __syncthreads();

        float (*Xs)[34] = (float(*)[34])sm_raw;                 // 8704B
        float* W1s = (float*)(sm_raw + 8704);                   // 16384B
        float* W2s = (float*)(sm_raw + 25088);                  // 16384B
        float* bs  = (float*)(sm_raw + 41472);                  // 256B
        float* bzs = (float*)(sm_raw + 41728);                  // 256B
        float* degs = (float*)(sm_raw + 41984);                 // 128B

        int row0 = (b - NNODEG) * 32;
        for (int i = tid; i < 1024; i += 256) {
            ((float4*)W1s)[i] = ((const float4*)g_W1T)[i];
            ((float4*)W2s)[i] = ((const float4*)g_W1Bf)[i];
        }
        if (tid < 64) {
            bs[tid] = W1_b[tid];
            bzs[tid] = g_bZ[tid];
        } else if (tid < 96) {
            degs[tid - 64] = (float)g_cnt[row0 + tid - 64];
        }
        #pragma unroll
        for (int i = 0; i < 2; i++) {
            int f = tid + i * 256;
            int r = f >> 4, k4 = f & 15;
            float4 x = ((const float4*)g_Xsum)[(size_t)(row0 + r) * 16 + k4];
            Xs[k4 * 4 + 0][r] = x.x; Xs[k4 * 4 + 1][r] = x.y;
            Xs[k4 * 4 + 2][r] = x.z; Xs[k4 * 4 + 3][r] = x.w;
        }
        __syncthreads();

        int tx = tid & 15, ty = tid >> 4;
        int tx4 = tx * 4, ty2 = ty * 2;
        float a1[2][4] = {}, a2[2][4] = {};
        #pragma unroll 16
        for (int k = 0; k < 64; k++) {
            float2 a = *(const float2*)&Xs[k][ty2];
            float4 w1 = *(const float4*)&W1s[k * 64 + tx4];
            float4 w2 = *(const float4*)&W2s[k * 64 + tx4];
            a1[0][0] += a.x * w1.x; a1[0][1] += a.x * w1.y;
            a1[0][2] += a.x * w1.z; a1[0][3] += a.x * w1.w;
            a1[1][0] += a.y * w1.x; a1[1][1] += a.y * w1.y;
            a1[1][2] += a.y * w1.z; a1[1][3] += a.y * w1.w;
            a2[0][0] += a.x * w2.x; a2[0][1] += a.x * w2.y;
            a2[0][2] += a.x * w2.z; a2[0][3] += a.x * w2.w;
            a2[1][0] += a.y * w2.x; a2[1][1] += a.y * w2.y;
            a2[1][2] += a.y * w2.z; a2[1][3] += a.y * w2.w;
        }
        #pragma unroll
        for (int r = 0; r < 2; r++) {
            int row = row0 + ty2 + r;
            float dg = degs[ty2 + r];
            float4 xe = make_float4(a1[r][0] + dg * bs[tx4 + 0],
                                    a1[r][1] + dg * bs[tx4 + 1],
                                    a1[r][2] + dg * bs[tx4 + 2],
                                    a1[r][3] + dg * bs[tx4 + 3]);
            float4 z  = make_float4(a2[r][0] + dg * bzs[tx4 + 0],
                                    a2[r][1] + dg * bzs[tx4 + 1],
                                    a2[r][2] + dg * bzs[tx4 + 2],
                                    a2[r][3] + dg * bzs[tx4 + 3]);
            ((float4*)XeOut)[(size_t)row * 16 + tx] = xe;
            ((float4*)g_Z)[(size_t)row * 16 + tx]   = z;
        }
        GDC_LAUNCH_DEPENDENTS();
        return;
    }

    // ------------- node GEMM: 64-row tile, 4 rows x 4 cols f32x2 -------------
    float* Xs = (float*)sm_raw;                                     // [64][68] 17408B
    unsigned long long* Wd = (unsigned long long*)(sm_raw + 17408); // [64][64] dup
    float* cv = (float*)(sm_raw + 50176);                           // [64] 0.5*cvec
    float* bb = (float*)(sm_raw + 50432);                           // [64] Wb

    int row0 = b * 64;
    if (tid < 64) cv[tid] = 0.5f * g_cvec[tid];
    else if (tid < 128) bb[tid - 64] = Wb[tid - 64];

    int tx = tid & 15, ty = tid >> 4;
    int ty4 = ty * 4;
    int c0 = 2 * tx;          // cols: c0, c0+1, c0+32, c0+33

    #pragma unroll
    for (int ph = 0; ph < 2; ph++) {
        const float* src = (ph == 0) ? X : X0;
        #pragma unroll
        for (int i = 0; i < 4; i++) {
            int f = tid + i * 256;
            int r = f >> 4, k4 = f & 15;
            int row = row0 + r;
            float4 x = (row < N_NODES) ? ((const float4*)src)[(size_t)row * 16 + k4]
                                       : make_float4(0.f, 0.f, 0.f, 0.f);
            Xs[(k4 * 4 + 0) * 68 + r] = 0.5f * x.x;
            Xs[(k4 * 4 + 1) * 68 + r] = 0.5f * x.y;
            Xs[(k4 * 4 + 2) * 68 + r] = 0.5f * x.z;
            Xs[(k4 * 4 + 3) * 68 + r] = 0.5f * x.w;
        }
        for (int i = tid; i < 4096; i += 256) {
            float w = g_WcatA[ph * 4096 + i];
            ((float2*)Wd)[i] = make_float2(w, w);
        }
        __syncthreads();

        unsigned long long acc[2][4];
        #pragma unroll
        for (int p = 0; p < 2; p++)
            #pragma unroll
            for (int c = 0; c < 4; c++) acc[p][c] = 0ULL;

        #pragma unroll 16
        for (int k = 0; k < 64; k++) {
            ulonglong2 a   = *(const ulonglong2*)(Xs + k * 68 + ty4);   // row pairs
            ulonglong2 b01 = *(const ulonglong2*)(Wd + k * 64 + c0);    // cols c0,c0+1
            ulonglong2 b23 = *(const ulonglong2*)(Wd + k * 64 + 32 + c0);
            FMA_X2(acc[0][0], a.x, b01.x); FMA_X2(acc[0][1], a.x, b01.y);
            FMA_X2(acc[0][2], a.x, b23.x); FMA_X2(acc[0][3], a.x, b23.y);
            FMA_X2(acc[1][0], a.y, b01.x); FMA_X2(acc[1][1], a.y, b01.y);
            FMA_X2(acc[1][2], a.y, b23.x); FMA_X2(acc[1][3], a.y, b23.y);
        }
        __syncthreads();   // FMA reads done before next-phase reload

        float* dst = (ph == 0) ? g_P1 : g_P2;
        const float* addv = (ph == 0) ? cv : bb;
        float adA = addv[c0], adB = addv[c0 + 1];
        float adC = addv[c0 + 32], adD = addv[c0 + 33];
        #pragma unroll
        for (int p = 0; p < 2; p++) {
            float lo[4], hi[4];
            #pragma unroll
            for (int c = 0; c < 4; c++)
                asm("mov.b64 {%0, %1}, %2;" : "=f"(lo[c]), "=f"(hi[c]) : "l"(acc[p][c]));
            int row_lo = row0 + ty4 + 2 * p;
            int row_hi = row_lo + 1;
            if (row_lo < N_NODES) {
                *(float2*)(dst + (size_t)row_lo * 64 + c0)      = make_float2(lo[0] + adA, lo[1] + adB);
                *(float2*)(dst + (size_t)row_lo * 64 + c0 + 32) = make_float2(lo[2] + adC, lo[3] + adD);
            }
            if (row_hi < N_NODES) {
                *(float2*)(dst + (size_t)row_hi * 64 + c0)      = make_float2(hi[0] + adA, hi[1] + adB);
                *(float2*)(dst + (size_t)row_hi * 64 + c0 + 32) = make_float2(hi[2] + adC, hi[3] + adD);
            }
        }
    }
    GDC_LAUNCH_DEPENDENTS();
}

// ---------------------------------------------------------------------------
// k_gatherv_out (PDL over fat3):
// out[v] = deg_v * P1[v] + P2[v] + 0.5 * sum(Z[e] over adj_v[v])
// ---------------------------------------------------------------------------
__global__ __launch_bounds__(256) void k_gatherv_out(float* __restrict__ out) {
    GDC_WAIT();   // all fat3 writes (g_Z, g_P1, g_P2) visible
    int t = threadIdx.x;
    int seg = blockIdx.x * 16 + (t >> 4);
    int lane = t & 15;
    int dtrue = g_cnt[N_EDGES + seg];
    int d = dtrue > VSTRIDE ? VSTRIDE : dtrue;
    float4 acc = gather_rows(g_adj_v + seg * VSTRIDE, d, (const float4*)g_Z, lane);
    float deg = (float)dtrue;
    float4 p1 = ((const float4*)g_P1)[(size_t)seg * 16 + lane];
    float4 p2 = ((const float4*)g_P2)[(size_t)seg * 16 + lane];
    float4 o;
    o.x = deg * p1.x + p2.x + 0.5f * acc.x;
    o.y = deg * p1.y + p2.y + 0.5f * acc.y;
    o.z = deg * p1.z + p2.z + 0.5f * acc.z;
    o.w = deg * p1.w + p2.w + 0.5f * acc.w;
    ((float4*)out)[(size_t)seg * 16 + lane] = o;
}

// ---------------------------------------------------------------------------
extern "C" void kernel_launch(void* const* d_in, const int* in_sizes, int n_in,
                              void* d_out, int out_size) {
    const float* X      = (const float*)d_in[0];
    const float* X0     = (const float*)d_in[1];
    const int*   vertex = (const int*)d_in[2];
    const int*   edges  = (const int*)d_in[3];
    const float* W1_w   = (const float*)d_in[4];
    const float* W1_b   = (const float*)d_in[5];
    const float* W2_w   = (const float*)d_in[6];
    const float* W2_b   = (const float*)d_in[7];
    const float* W_w    = (const float*)d_in[8];
    const float* W_b    = (const float*)d_in[9];

    float* out   = (float*)d_out;                       // [N_NODES, 64]
    float* XeOut = (float*)d_out + (size_t)N_NODES * D; // [N_EDGES, 64]

    cudaFuncSetAttribute(k_fat3, cudaFuncAttributeMaxDynamicSharedMemorySize,
                         FAT3_SMEM);

    void* cntP = nullptr;
    cudaGetSymbolAddress(&cntP, g_cnt);
    cudaMemsetAsync(cntP, 0, (size_t)(N_EDGES + N_NODES + 1) * sizeof(int), 0);

    k_fat1<<<NPRE + NFILL, 256>>>(vertex, edges, W1_w, W2_w, W2_b, W_w);

    cudaLaunchAttribute pdl[1];
    pdl[0].id = cudaLaunchAttributeProgrammaticStreamSerialization;
    pdl[0].val.programmaticStreamSerializationAllowed = 1;

    {   // fat2b: PDL over fat1 (waits internally, then releases fat3)
        cudaLaunchConfig_t cfg = {};
        cfg.gridDim = dim3(NPRE2 + NGE);
        cfg.blockDim = dim3(256);
        cfg.stream = 0;
        cfg.attrs = pdl;
        cfg.numAttrs = 1;
        cudaLaunchKernelEx(&cfg, k_fat2b, X, W1_b);
    }
    {   // fat3: PDL over fat2b (node blocks overlap gather_e; edge blocks
        // acquire-spin on the fat2b completion flag)
        cudaLaunchConfig_t cfg = {};
        cfg.gridDim = dim3(NNODEG + NEDGEG);
        cfg.blockDim = dim3(256);
        cfg.dynamicSmemBytes = FAT3_SMEM;
        cfg.stream = 0;
        cfg.attrs = pdl;
        cfg.numAttrs = 1;
        cudaLaunchKernelEx(&cfg, k_fat3, X, X0, W1_b, W_b, XeOut);
    }
    {   // gatherv_out: PDL over fat3
        cudaLaunchConfig_t cfg = {};
        cfg.gridDim = dim3(N_NODES / 16);
        cfg.blockDim = dim3(256);
        cfg.stream = 0;
        cfg.attrs = pdl;
        cfg.numAttrs = 1;
        cudaLaunchKernelEx(&cfg, k_gatherv_out, out);
    }
}